// round 11
// baseline (speedup 1.0000x reference)
#include <cuda_runtime.h>
#include <cuda_bf16.h>

#define HASH_SIZE 256
#define OFFSET_SIZE 64
#define OFFSET_ENTRIES (OFFSET_SIZE * OFFSET_SIZE * OFFSET_SIZE)

// 1MB packed offset table: one uint32 per entry, f0 | f1<<8 | f2<<16.
// Offsets are only ever used mod 256, so 8 bits per component is lossless.
__device__ unsigned int g_packed_offsets[OFFSET_ENTRIES];

// L2 evict-last policy: applied to BOTH reuse-bearing structures — the 1MB
// packed offset table (hot, always re-touched) and the hash-table lines
// (birthday-collision reuse: ~1.4M of 4M gathers re-touch a line).
__device__ __forceinline__ long long make_evict_last_policy() {
    long long p;
    asm("createpolicy.fractional.L2::evict_last.b64 %0, 1.0;" : "=l"(p));
    return p;
}

__device__ __forceinline__ unsigned int ldg_hint_u32(const unsigned int* ptr, long long pol) {
    unsigned int v;
    asm volatile("ld.global.L2::cache_hint.u32 %0, [%1], %2;"
                 : "=r"(v) : "l"(ptr), "l"(pol));
    return v;
}

__device__ __forceinline__ float4 ldg_hint_f4(const float4* ptr, long long pol) {
    float4 v;
    asm volatile("ld.global.L2::cache_hint.v4.f32 {%0,%1,%2,%3}, [%4], %5;"
                 : "=f"(v.x), "=f"(v.y), "=f"(v.z), "=f"(v.w)
                 : "l"(ptr), "l"(pol));
    return v;
}

// Prologue: pack [64^3][3] int32 -> [64^3] uint32 (bytes).
__global__ __launch_bounds__(256) void pack_offsets_kernel(
    const int* __restrict__ offset_table)
{
    int e = blockIdx.x * blockDim.x + threadIdx.x;
    if (e >= OFFSET_ENTRIES) return;
    const int f0 = offset_table[3 * e + 0] & 0xFF;
    const int f1 = offset_table[3 * e + 1] & 0xFF;
    const int f2 = offset_table[3 * e + 2] & 0xFF;
    g_packed_offsets[e] = (unsigned int)(f0 | (f1 << 8) | (f2 << 16));
}

__global__ __launch_bounds__(256) void psh_kernel(
    const int*    __restrict__ coords,       // [N,3] int32
    const float4* __restrict__ hash_table,   // [256,256,256,8] f32 as float4 pairs
    const float*  __restrict__ m0,           // [3]
    const float*  __restrict__ m1,           // [3]
    float4*       __restrict__ out,          // [N,8] f32 as float4 pairs
    int n)
{
    const float m0x = m0[0], m0y = m0[1], m0z = m0[2];
    const float m1x = m1[0], m1y = m1[1], m1z = m1[2];

    int i = blockIdx.x * blockDim.x + threadIdx.x;
    if (i >= n) return;

    const long long pol = make_evict_last_policy();

    // --- coords: dense, read-once -> streaming loads ---
    const int c0 = __ldcs(&coords[3 * i + 0]);
    const int c1 = __ldcs(&coords[3 * i + 1]);
    const int c2 = __ldcs(&coords[3 * i + 2]);

    // --- offset-table index: (int)(c * m1) & 63 (& == floor-mod for pow2) ---
    const int o0 = ((int)((float)c0 * m1x)) & (OFFSET_SIZE - 1);
    const int o1 = ((int)((float)c1 * m1y)) & (OFFSET_SIZE - 1);
    const int o2 = ((int)((float)c2 * m1z)) & (OFFSET_SIZE - 1);
    const int oent = (((o0 << 6) | o1) << 6) | o2;

    // --- single 4B gather into the 1MB packed table (L2-resident) ---
    const unsigned int pf = ldg_hint_u32(&g_packed_offsets[oent], pol);
    const int f0 = (int)(pf & 0xFFu);
    const int f1 = (int)((pf >> 8) & 0xFFu);
    const int f2 = (int)((pf >> 16) & 0xFFu);

    // --- hash index: ((int)(c * m0) + off) & 255 (& == floor-mod for pow2) ---
    const int h0 = (((int)((float)c0 * m0x)) + f0) & (HASH_SIZE - 1);
    const int h1 = (((int)((float)c1 * m0y)) + f1) & (HASH_SIZE - 1);
    const int h2 = (((int)((float)c2 * m0z)) + f2) & (HASH_SIZE - 1);

    const long long row = (long long)((((h0 << 8) | h1) << 8) | h2) * 2;

    // --- hash gather: 32B row, evict_last so line-reuse survives in L2 ---
    const float4 a = ldg_hint_f4(&hash_table[row + 0], pol);
    const float4 b = ldg_hint_f4(&hash_table[row + 1], pol);

    // --- output: write-once -> streaming stores ---
    const long long ob = 2ll * i;
    __stcs(&out[ob + 0], a);
    __stcs(&out[ob + 1], b);
}

extern "C" void kernel_launch(void* const* d_in, const int* in_sizes, int n_in,
                              void* d_out, int out_size) {
    const int*    coords       = (const int*)d_in[0];
    const float4* hash_table   = (const float4*)d_in[1];
    const int*    offset_table = (const int*)d_in[2];
    const float*  m0           = (const float*)d_in[3];
    const float*  m1           = (const float*)d_in[4];
    float4*       out          = (float4*)d_out;

    // Prologue: pack the offset table (262144 entries).
    pack_offsets_kernel<<<(OFFSET_ENTRIES + 255) / 256, 256>>>(offset_table);

    const int n = in_sizes[0] / 3;  // number of queries
    const int threads = 256;
    const int blocks = (n + threads - 1) / threads;
    psh_kernel<<<blocks, threads>>>(coords, hash_table, m0, m1, out, n);
}

// round 13
// speedup vs baseline: 1.0003x; 1.0003x over previous
#include <cuda_runtime.h>
#include <cuda_bf16.h>

#define HASH_SIZE 256
#define OFFSET_SIZE 64
#define OFFSET_ENTRIES (OFFSET_SIZE * OFFSET_SIZE * OFFSET_SIZE)

// 1MB packed offset table: one uint32 per entry, f0 | f1<<8 | f2<<16.
// Offsets are only ever used mod 256, so 8 bits per component is lossless.
__device__ unsigned int g_packed_offsets[OFFSET_ENTRIES];

// L2 evict-last policy — ONLY for the 1MB packed offset table (hot, heavy
// reuse). R11 A/B proved applying it to the streaming hash gathers regresses.
__device__ __forceinline__ long long make_evict_last_policy() {
    long long p;
    asm("createpolicy.fractional.L2::evict_last.b64 %0, 1.0;" : "=l"(p));
    return p;
}

__device__ __forceinline__ unsigned int ldg_hint_u32(const unsigned int* ptr, long long pol) {
    unsigned int v;
    asm volatile("ld.global.L2::cache_hint.u32 %0, [%1], %2;"
                 : "=r"(v) : "l"(ptr), "l"(pol));
    return v;
}

// Prologue: pack [64^3][3] int32 -> [64^3] uint32. Vectorized: each thread
// packs 4 entries from three int4 loads (48B) into one uint4 store (16B).
__global__ __launch_bounds__(256) void pack_offsets_kernel(
    const int4* __restrict__ offset_table4)   // [64^3 * 3 / 4] int4
{
    int t = blockIdx.x * blockDim.x + threadIdx.x;       // 65536 threads
    if (t >= OFFSET_ENTRIES / 4) return;

    const int4 w0 = __ldcs(&offset_table4[3 * t + 0]);   // e0.f0 e0.f1 e0.f2 e1.f0
    const int4 w1 = __ldcs(&offset_table4[3 * t + 1]);   // e1.f1 e1.f2 e2.f0 e2.f1
    const int4 w2 = __ldcs(&offset_table4[3 * t + 2]);   // e2.f2 e3.f0 e3.f1 e3.f2

    uint4 p;
    p.x = (unsigned)((w0.x & 0xFF) | ((w0.y & 0xFF) << 8) | ((w0.z & 0xFF) << 16));
    p.y = (unsigned)((w0.w & 0xFF) | ((w1.x & 0xFF) << 8) | ((w1.y & 0xFF) << 16));
    p.z = (unsigned)((w1.z & 0xFF) | ((w1.w & 0xFF) << 8) | ((w2.x & 0xFF) << 16));
    p.w = (unsigned)((w2.y & 0xFF) | ((w2.z & 0xFF) << 8) | ((w2.w & 0xFF) << 16));

    *reinterpret_cast<uint4*>(&g_packed_offsets[4 * t]) = p;
}

__global__ __launch_bounds__(256) void psh_kernel(
    const int*    __restrict__ coords,       // [N,3] int32
    const float4* __restrict__ hash_table,   // [256,256,256,8] f32 as float4 pairs
    const float*  __restrict__ m0,           // [3]
    const float*  __restrict__ m1,           // [3]
    float4*       __restrict__ out,          // [N,8] f32 as float4 pairs
    int n)
{
    const float m0x = m0[0], m0y = m0[1], m0z = m0[2];
    const float m1x = m1[0], m1y = m1[1], m1z = m1[2];

    int i = blockIdx.x * blockDim.x + threadIdx.x;
    if (i >= n) return;

    const long long pol = make_evict_last_policy();

    // --- coords: dense, read-once -> streaming loads ---
    const int c0 = __ldcs(&coords[3 * i + 0]);
    const int c1 = __ldcs(&coords[3 * i + 1]);
    const int c2 = __ldcs(&coords[3 * i + 2]);

    // --- offset-table index: (int)(c * m1) & 63 (& == floor-mod for pow2) ---
    const int o0 = ((int)((float)c0 * m1x)) & (OFFSET_SIZE - 1);
    const int o1 = ((int)((float)c1 * m1y)) & (OFFSET_SIZE - 1);
    const int o2 = ((int)((float)c2 * m1z)) & (OFFSET_SIZE - 1);
    const int oent = (((o0 << 6) | o1) << 6) | o2;

    // --- single 4B gather into the 1MB packed table (L2-resident, evict_last) ---
    const unsigned int pf = ldg_hint_u32(&g_packed_offsets[oent], pol);
    const int f0 = (int)(pf & 0xFFu);
    const int f1 = (int)((pf >> 8) & 0xFFu);
    const int f2 = (int)((pf >> 16) & 0xFFu);

    // --- hash index: ((int)(c * m0) + off) & 255 (& == floor-mod for pow2) ---
    const int h0 = (((int)((float)c0 * m0x)) + f0) & (HASH_SIZE - 1);
    const int h1 = (((int)((float)c1 * m0y)) + f1) & (HASH_SIZE - 1);
    const int h2 = (((int)((float)c2 * m0z)) + f2) & (HASH_SIZE - 1);

    const long long row = (long long)((((h0 << 8) | h1) << 8) | h2) * 2;

    // --- hash gather: 32B row, DEFAULT policy (best in A/B; evict_first and
    //     evict_last both regressed) ---
    const float4 a = __ldg(&hash_table[row + 0]);
    const float4 b = __ldg(&hash_table[row + 1]);

    // --- output: write-once -> streaming stores ---
    const long long ob = 2ll * i;
    __stcs(&out[ob + 0], a);
    __stcs(&out[ob + 1], b);
}

extern "C" void kernel_launch(void* const* d_in, const int* in_sizes, int n_in,
                              void* d_out, int out_size) {
    const int*    coords       = (const int*)d_in[0];
    const float4* hash_table   = (const float4*)d_in[1];
    const int4*   offset_table = (const int4*)d_in[2];
    const float*  m0           = (const float*)d_in[3];
    const float*  m1           = (const float*)d_in[4];
    float4*       out          = (float4*)d_out;

    // Prologue: pack the offset table (65536 threads, 4 entries each).
    pack_offsets_kernel<<<(OFFSET_ENTRIES / 4 + 255) / 256, 256>>>(offset_table);

    const int n = in_sizes[0] / 3;  // number of queries
    const int threads = 256;
    const int blocks = (n + threads - 1) / threads;
    psh_kernel<<<blocks, threads>>>(coords, hash_table, m0, m1, out, n);
}